// round 6
// baseline (speedup 1.0000x reference)
#include <cuda_runtime.h>
#include <cuda_bf16.h>
#include <math.h>
#include <stdint.h>

#define BB 32
#define SS 8192
#define DD 256
#define HH 256

#define ROWS_T 32            // rows computed by tensor (HMMA) half
#define ROWS_F 16            // rows computed by FFMA half
#define TILE   (ROWS_T + ROWS_F)
#define NBLK   ((SS + TILE - 1) / TILE)   // 171

// device-global scratch (allocation-free rule)
__device__ float g_inp[BB * HH];
__device__ float g_Wt[DD * HH];              // W_ctx^T fp32, [d][h]
__device__ __nv_bfloat16 g_Bh[HH * DD];      // W_ctx hi bf16, [h][d]
__device__ __nv_bfloat16 g_Bl[HH * DD];      // W_ctx lo
__device__ float g_att[BB * SS];

// ---------------------------------------------------------------------------
__device__ __forceinline__ uint32_t smem_u32(const void* p) {
    uint32_t a;
    asm("{ .reg .u64 t; cvta.to.shared.u64 t, %1; cvt.u32.u64 %0, t; }" : "=r"(a) : "l"(p));
    return a;
}
#define CP_ASYNC16(dst, src) \
    asm volatile("cp.async.cg.shared.global [%0], [%1], 16;" :: "r"(dst), "l"(src))
#define CP_COMMIT() asm volatile("cp.async.commit_group;" ::: "memory")
#define CP_WAIT0()  asm volatile("cp.async.wait_group 0;" ::: "memory")

#define LDSM4(r0, r1, r2, r3, a) \
    asm volatile("ldmatrix.sync.aligned.m8n8.x4.shared.b16 {%0,%1,%2,%3}, [%4];" \
        : "=r"(r0), "=r"(r1), "=r"(r2), "=r"(r3) : "r"(a))

#define MMA_BF16(c, A, b0, b1) \
    asm volatile("mma.sync.aligned.m16n8k16.row.col.f32.bf16.bf16.f32 " \
        "{%0,%1,%2,%3},{%4,%5,%6,%7},{%8,%9},{%0,%1,%2,%3};" \
        : "+f"((c)[0]), "+f"((c)[1]), "+f"((c)[2]), "+f"((c)[3]) \
        : "r"((A)[0]), "r"((A)[1]), "r"((A)[2]), "r"((A)[3]), "r"(b0), "r"(b1))

// ---------------------------------------------------------------------------
// smem byte offsets
// ---------------------------------------------------------------------------
#define PITCH 80
#define OFF_AT  0                         // HMMA A bf16: 2 st x (hi 2560 + lo 2560)
#define OFF_B   10240                     // B bf16: 2 st x 2 mats x 20480
#define OFF_BF  92160                     // B fp32: 2 st x 32768   [k][n]
#define OFF_AF  157696                    // FFMA A fp32: 2 st x 2048 [row][k]
#define OFF_IB  161792
#define OFF_V   162816
#define OFF_P   163840                    // 32 rows x 4 warp-cols
#define SMEM_TOTAL 164352

// ---------------------------------------------------------------------------
// Kernel 1: inp = x @ W_in^T + b_in
// ---------------------------------------------------------------------------
__global__ void k_inp(const float* __restrict__ x, const float* __restrict__ W_in,
                      const float* __restrict__ b_in) {
    int b = blockIdx.x, h = threadIdx.x;
    __shared__ float xs[HH];
    xs[h] = x[b * HH + h];
    __syncthreads();
    float acc = b_in[h];
    const float* w = W_in + h * HH;
#pragma unroll 8
    for (int d0 = 0; d0 < HH; d0 += 4) {
        float4 w4 = *(const float4*)(w + d0);
        acc += xs[d0] * w4.x + xs[d0+1] * w4.y + xs[d0+2] * w4.z + xs[d0+3] * w4.w;
    }
    g_inp[b * HH + h] = acc;
}

// ---------------------------------------------------------------------------
// Kernel 2: split W -> bf16 hi/lo, and transpose to g_Wt fp32
// ---------------------------------------------------------------------------
__global__ void k_wsplit(const float* __restrict__ W) {
    int i = blockIdx.x * 256 + threadIdx.x;
    float v = W[i];
    __nv_bfloat16 h = __float2bfloat16_rn(v);
    g_Bh[i] = h;
    g_Bl[i] = __float2bfloat16_rn(v - __bfloat162float(h));
}
__global__ void k_transpose(const float* __restrict__ W) {
    __shared__ float t[32][33];
    int h0 = blockIdx.x * 32, d0 = blockIdx.y * 32;
    t[threadIdx.y][threadIdx.x] = W[(h0 + threadIdx.y) * DD + d0 + threadIdx.x];
    __syncthreads();
    g_Wt[(d0 + threadIdx.y) * HH + h0 + threadIdx.x] = t[threadIdx.x][threadIdx.y];
}

// ---------------------------------------------------------------------------
// Kernel 3: hybrid tensor+FFMA fused GEMM + tanh-dot epilogue.
// 512 threads: warps 0-7 HMMA (rows 0..31), warps 8-15 FFMA fp32 (rows 32..47).
// ---------------------------------------------------------------------------
__global__ __launch_bounds__(512, 1) void k_main(const float* __restrict__ context,
                                                 const float* __restrict__ b_ctx,
                                                 const float* __restrict__ V) {
    extern __shared__ char smem[];
    uint32_t sb = smem_u32(smem);
    int tid = threadIdx.x, wid = tid >> 5, lid = tid & 31;
    int b = blockIdx.y;
    int m0 = blockIdx.x * TILE;

    float* ibs = (float*)(smem + OFF_IB);
    float* vvs = (float*)(smem + OFF_V);
    if (tid < 256) {
        ibs[tid] = g_inp[b * HH + tid] + b_ctx[tid];
        vvs[tid] = V[tid];
    }
    const float* ctx = context + ((long)b * SS + m0) * DD;

    // ---- shared cp.async issue (B bf16 + B fp32 for stage, all 512 threads;
    //      FFMA-A by threads 256-383) ----
#define ISSUE_STAGE(k0, st)                                                        \
    {                                                                              \
        _Pragma("unroll")                                                          \
        for (int r = 0; r < 4; r++) {                                              \
            int idx = tid + 512 * r;                                               \
            int mat = idx >> 10, rem = idx & 1023;                                 \
            int row = rem >> 2, cc = rem & 3;                                      \
            const __nv_bfloat16* src = (mat ? g_Bl : g_Bh) + row * DD + (k0) + cc * 8; \
            uint32_t dst = sb + OFF_B + (st) * 40960 + mat * 20480 + row * PITCH + cc * 16; \
            CP_ASYNC16(dst, src);                                                  \
        }                                                                          \
        _Pragma("unroll")                                                          \
        for (int r = 0; r < 4; r++) {                                              \
            int idx = tid + 512 * r;                                               \
            int kk = idx >> 6, cc = idx & 63;                                      \
            const float* src = g_Wt + ((k0) + kk) * HH + cc * 4;                   \
            uint32_t dst = sb + OFF_BF + (st) * 32768 + kk * 1024 + cc * 16;       \
            CP_ASYNC16(dst, src);                                                  \
        }                                                                          \
        if (tid >= 256 && tid < 384) {                                             \
            int i2 = tid - 256;                                                    \
            int row = i2 >> 3, cc = i2 & 7;                                        \
            int rg = ROWS_T + row;                                                 \
            if (m0 + rg >= SS) rg = 0;                                             \
            const float* src = ctx + rg * DD + (k0) + cc * 4;                      \
            uint32_t dst = sb + OFF_AF + (st) * 2048 + row * 128 + cc * 16;        \
            CP_ASYNC16(dst, src);                                                  \
        }                                                                          \
        CP_COMMIT();                                                               \
    }

    ISSUE_STAGE(0, 0)

    if (tid < 256) {
        // =================== HMMA half: rows 0..31 ===================
        int wr = wid & 1, wc = wid >> 1;     // 2 x 4 warp grid over 32x256
        int arow = tid >> 3, aseg = tid & 7; // A stage: 1 float4 per thread
        float4 a4 = *(const float4*)(ctx + arow * DD + aseg * 4);

        float c[8][4];
#pragma unroll
        for (int j = 0; j < 8; j++)
#pragma unroll
            for (int e = 0; e < 4; e++) c[j][e] = 0.f;

        for (int kt = 0; kt < DD / 32; kt++) {
            int s = kt & 1;
            // convert prefetched A into stage s (hi at +0, lo at +2560)
            {
                __nv_bfloat16 h0 = __float2bfloat16_rn(a4.x);
                __nv_bfloat16 h1 = __float2bfloat16_rn(a4.y);
                __nv_bfloat16 h2 = __float2bfloat16_rn(a4.z);
                __nv_bfloat16 h3 = __float2bfloat16_rn(a4.w);
                __nv_bfloat16 l0 = __float2bfloat16_rn(a4.x - __bfloat162float(h0));
                __nv_bfloat16 l1 = __float2bfloat16_rn(a4.y - __bfloat162float(h1));
                __nv_bfloat16 l2 = __float2bfloat16_rn(a4.z - __bfloat162float(h2));
                __nv_bfloat16 l3 = __float2bfloat16_rn(a4.w - __bfloat162float(h3));
                uint2 ph = make_uint2(
                    (uint32_t)__bfloat16_as_ushort(h0) | ((uint32_t)__bfloat16_as_ushort(h1) << 16),
                    (uint32_t)__bfloat16_as_ushort(h2) | ((uint32_t)__bfloat16_as_ushort(h3) << 16));
                uint2 pl = make_uint2(
                    (uint32_t)__bfloat16_as_ushort(l0) | ((uint32_t)__bfloat16_as_ushort(l1) << 16),
                    (uint32_t)__bfloat16_as_ushort(l2) | ((uint32_t)__bfloat16_as_ushort(l3) << 16));
                char* base = smem + OFF_AT + s * 5120 + arow * PITCH + aseg * 8;
                *(uint2*)(base)        = ph;
                *(uint2*)(base + 2560) = pl;
            }
            CP_WAIT0();
            __syncthreads();
            if (kt < DD / 32 - 1) {
                int k0n = (kt + 1) * 32;
                ISSUE_STAGE(k0n, s ^ 1)
                a4 = *(const float4*)(ctx + arow * DD + k0n + aseg * 4);
            }
            uint32_t abase = sb + OFF_AT + s * 5120;
            uint32_t bbase = sb + OFF_B + s * 40960;
#pragma unroll
            for (int ks = 0; ks < 2; ks++) {
                uint32_t aH[4], aL[4], bH[4][4], bL[4][4];
                int arow_f = wr * 16 + (lid & 15);
                int acol_b = ks * 32 + (lid >> 4) * 16;
                uint32_t ad = abase + arow_f * PITCH + acol_b;
                LDSM4(aH[0], aH[1], aH[2], aH[3], ad);
                LDSM4(aL[0], aL[1], aL[2], aL[3], ad + 2560);
                int brow_f = wc * 64 + (lid & 7) + ((lid >> 4) * 8);
                int bcol_b = ks * 32 + ((lid >> 3) & 1) * 16;
#pragma unroll
                for (int jp = 0; jp < 4; jp++) {
                    uint32_t bd = bbase + (brow_f + jp * 16) * PITCH + bcol_b;
                    LDSM4(bH[jp][0], bH[jp][1], bH[jp][2], bH[jp][3], bd);
                    LDSM4(bL[jp][0], bL[jp][1], bL[jp][2], bL[jp][3], bd + 20480);
                }
#pragma unroll
                for (int j = 0; j < 8; j++) {
                    uint32_t h0 = bH[j >> 1][(j & 1) * 2], h1 = bH[j >> 1][(j & 1) * 2 + 1];
                    uint32_t l0 = bL[j >> 1][(j & 1) * 2], l1 = bL[j >> 1][(j & 1) * 2 + 1];
                    MMA_BF16(c[j], aH, h0, h1);
                    MMA_BF16(c[j], aH, l0, l1);
                    MMA_BF16(c[j], aL, h0, h1);
                }
            }
        }
        // epilogue: rows = wr*16 + (lid>>2) + half*8; cols = wc*64 + j*8 + (lid&3)*2 + e
        {
            int q = lid & 3, g = lid >> 2;
            float p0 = 0.f, p1 = 0.f;
#pragma unroll
            for (int j = 0; j < 8; j++) {
                int h0 = wc * 64 + j * 8 + q * 2;
                p0 += vvs[h0]   * tanhf(c[j][0] + ibs[h0]);
                p0 += vvs[h0+1] * tanhf(c[j][1] + ibs[h0+1]);
                p1 += vvs[h0]   * tanhf(c[j][2] + ibs[h0]);
                p1 += vvs[h0+1] * tanhf(c[j][3] + ibs[h0+1]);
            }
#pragma unroll
            for (int off = 1; off <= 2; off <<= 1) {
                p0 += __shfl_xor_sync(0xffffffffu, p0, off);
                p1 += __shfl_xor_sync(0xffffffffu, p1, off);
            }
            float* part = (float*)(smem + OFF_P);
            if (q == 0) {
                part[(wr * 16 + g) * 4 + wc]     = p0;
                part[(wr * 16 + g + 8) * 4 + wc] = p1;
            }
        }
    } else {
        // =================== FFMA half: rows 32..47 ===================
        int fw = wid - 8;                     // 0..7, 2 rows each
        float accf[2][8];
#pragma unroll
        for (int rr = 0; rr < 2; rr++)
#pragma unroll
            for (int e = 0; e < 8; e++) accf[rr][e] = 0.f;

        for (int kt = 0; kt < DD / 32; kt++) {
            int s = kt & 1;
            CP_WAIT0();
            __syncthreads();
            if (kt < DD / 32 - 1) {
                int k0n = (kt + 1) * 32;
                ISSUE_STAGE(k0n, s ^ 1)
            }
            const float* Bf = (const float*)(smem + OFF_BF + s * 32768);
            const float* Af = (const float*)(smem + OFF_AF + s * 2048);
#pragma unroll
            for (int k = 0; k < 32; k++) {
                float a0 = Af[(fw * 2 + 0) * 32 + k];
                float a1 = Af[(fw * 2 + 1) * 32 + k];
                float4 b0 = *(const float4*)(Bf + k * 256 + lid * 4);
                float4 b1 = *(const float4*)(Bf + k * 256 + 128 + lid * 4);
                accf[0][0] += a0 * b0.x; accf[0][1] += a0 * b0.y;
                accf[0][2] += a0 * b0.z; accf[0][3] += a0 * b0.w;
                accf[0][4] += a0 * b1.x; accf[0][5] += a0 * b1.y;
                accf[0][6] += a0 * b1.z; accf[0][7] += a0 * b1.w;
                accf[1][0] += a1 * b0.x; accf[1][1] += a1 * b0.y;
                accf[1][2] += a1 * b0.z; accf[1][3] += a1 * b0.w;
                accf[1][4] += a1 * b1.x; accf[1][5] += a1 * b1.y;
                accf[1][6] += a1 * b1.z; accf[1][7] += a1 * b1.w;
            }
        }
        // epilogue: thread cols = {lid*4..+3} U {128+lid*4..+3}
        {
            float p0 = 0.f, p1 = 0.f;
#pragma unroll
            for (int e = 0; e < 4; e++) {
                int cA = lid * 4 + e, cB = 128 + lid * 4 + e;
                p0 += vvs[cA] * tanhf(accf[0][e]     + ibs[cA]);
                p0 += vvs[cB] * tanhf(accf[0][4 + e] + ibs[cB]);
                p1 += vvs[cA] * tanhf(accf[1][e]     + ibs[cA]);
                p1 += vvs[cB] * tanhf(accf[1][4 + e] + ibs[cB]);
            }
#pragma unroll
            for (int off = 16; off; off >>= 1) {
                p0 += __shfl_xor_sync(0xffffffffu, p0, off);
                p1 += __shfl_xor_sync(0xffffffffu, p1, off);
            }
            if (lid == 0) {
                int r0 = m0 + ROWS_T + fw * 2;
                if (r0     < SS) g_att[b * SS + r0]     = 10.f * tanhf(p0);
                if (r0 + 1 < SS) g_att[b * SS + r0 + 1] = 10.f * tanhf(p1);
            }
        }
    }

    __syncthreads();
    if (tid < ROWS_T) {
        const float* part = (const float*)(smem + OFF_P);
        float ssum = part[tid * 4] + part[tid * 4 + 1] + part[tid * 4 + 2] + part[tid * 4 + 3];
        g_att[b * SS + m0 + tid] = 10.f * tanhf(ssum);
    }
}

// ---------------------------------------------------------------------------
__global__ void k_echo(const int* __restrict__ mask, float* __restrict__ out) {
    int i = blockIdx.x * blockDim.x + threadIdx.x;
    out[2 * BB + i] = mask[i] ? 1.f : 0.f;
}

__global__ __launch_bounds__(1024) void k_reduce(const int* __restrict__ mask,
                                                 float* __restrict__ out) {
    int b = blockIdx.x, tid = threadIdx.x;
    __shared__ float smax[1024], ssum[1024];
    __shared__ int   sidx[1024];

    float best = -INFINITY, se = 0.f;
    int bidx = 0x7fffffff;
    for (int s = tid; s < SS; s += 1024) {
        if (mask[b * SS + s]) {
            float v = g_att[b * SS + s];
            se += expf(v);
            if (v > best || (v == best && s < bidx)) { best = v; bidx = s; }
        }
    }
    smax[tid] = best; sidx[tid] = bidx; ssum[tid] = se;
    __syncthreads();
    for (int off = 512; off; off >>= 1) {
        if (tid < off) {
            float v = smax[tid + off]; int ix = sidx[tid + off];
            if (v > smax[tid] || (v == smax[tid] && ix < sidx[tid])) {
                smax[tid] = v; sidx[tid] = ix;
            }
            ssum[tid] += ssum[tid + off];
        }
        __syncthreads();
    }
    if (tid == 0) {
        float rowmax = smax[0];
        out[b]      = (float)((rowmax == -INFINITY) ? 0 : sidx[0]);
        out[BB + b] = expf(rowmax) / ssum[0];
    }
}

// ---------------------------------------------------------------------------
extern "C" void kernel_launch(void* const* d_in, const int* in_sizes, int n_in,
                              void* d_out, int out_size) {
    const float* x      = (const float*)d_in[0];
    const float* contex = (const float*)d_in[1];
    const int*   mask   = (const int*)  d_in[2];
    const float* W_in   = (const float*)d_in[3];
    const float* b_in   = (const float*)d_in[4];
    const float* W_ctx  = (const float*)d_in[5];
    const float* b_ctx  = (const float*)d_in[6];
    const float* V      = (const float*)d_in[7];
    float* out = (float*)d_out;

    cudaFuncSetAttribute(k_main, cudaFuncAttributeMaxDynamicSharedMemorySize, SMEM_TOTAL);

    k_inp<<<BB, HH>>>(x, W_in, b_in);
    k_wsplit<<<HH * DD / 256, 256>>>(W_ctx);
    k_transpose<<<dim3(HH / 32, DD / 32), dim3(32, 32)>>>(W_ctx);
    k_main<<<dim3(NBLK, BB), 512, SMEM_TOTAL>>>(contex, b_ctx, V);
    k_echo<<<BB * SS / 256, 256>>>(mask, out);
    k_reduce<<<BB, 1024>>>(mask, out);
}

// round 7
// speedup vs baseline: 2.3045x; 2.3045x over previous
#include <cuda_runtime.h>
#include <cuda_bf16.h>
#include <math.h>
#include <stdint.h>

#define BB 32
#define SS 8192
#define DD 256
#define HH 256

// device-global scratch (allocation-free rule)
__device__ float g_inp[BB * HH];             // x @ W_in^T + b_in
__device__ __nv_bfloat16 g_Bh[HH * DD];      // W_ctx hi (bf16), [h][d]
__device__ __nv_bfloat16 g_Bl[HH * DD];      // W_ctx lo
__device__ float g_att[BB * SS];             // logits post 10*tanh

// ---------------------------------------------------------------------------
__device__ __forceinline__ uint32_t smem_u32(const void* p) {
    uint32_t a;
    asm("{ .reg .u64 t; cvta.to.shared.u64 t, %1; cvt.u32.u64 %0, t; }" : "=r"(a) : "l"(p));
    return a;
}
#define CP_ASYNC16(dst, src) \
    asm volatile("cp.async.cg.shared.global [%0], [%1], 16;" :: "r"(dst), "l"(src))
#define CP_COMMIT() asm volatile("cp.async.commit_group;" ::: "memory")
#define CP_WAIT0()  asm volatile("cp.async.wait_group 0;" ::: "memory")

#define LDSM4(r0, r1, r2, r3, a) \
    asm volatile("ldmatrix.sync.aligned.m8n8.x4.shared.b16 {%0,%1,%2,%3}, [%4];" \
        : "=r"(r0), "=r"(r1), "=r"(r2), "=r"(r3) : "r"(a))

#define MMA_BF16(c, A, b0, b1) \
    asm volatile("mma.sync.aligned.m16n8k16.row.col.f32.bf16.bf16.f32 " \
        "{%0,%1,%2,%3},{%4,%5,%6,%7},{%8,%9},{%0,%1,%2,%3};" \
        : "+f"((c)[0]), "+f"((c)[1]), "+f"((c)[2]), "+f"((c)[3]) \
        : "r"((A)[0]), "r"((A)[1]), "r"((A)[2]), "r"((A)[3]), "r"(b0), "r"(b1))

// ---------------------------------------------------------------------------
// Kernel 1: inp[b,h] = b_in[h] + sum_d x[b,d] * W_in[h,d]
// ---------------------------------------------------------------------------
__global__ void k_inp(const float* __restrict__ x, const float* __restrict__ W_in,
                      const float* __restrict__ b_in) {
    int b = blockIdx.x, h = threadIdx.x;
    __shared__ float xs[HH];
    xs[h] = x[b * HH + h];
    __syncthreads();
    float acc = b_in[h];
    const float* w = W_in + h * HH;
#pragma unroll 8
    for (int d0 = 0; d0 < HH; d0 += 4) {
        float4 w4 = *(const float4*)(w + d0);
        acc += xs[d0] * w4.x + xs[d0+1] * w4.y + xs[d0+2] * w4.z + xs[d0+3] * w4.w;
    }
    g_inp[b * HH + h] = acc;
}

// ---------------------------------------------------------------------------
// Kernel 2: split W_ctx fp32 -> bf16 hi/lo
// ---------------------------------------------------------------------------
__global__ void k_wsplit(const float* __restrict__ W) {
    int i = blockIdx.x * 256 + threadIdx.x;
    float v = W[i];
    __nv_bfloat16 h = __float2bfloat16_rn(v);
    g_Bh[i] = h;
    g_Bl[i] = __float2bfloat16_rn(v - __bfloat162float(h));
}

// ---------------------------------------------------------------------------
// Kernel 3: split-bf16 HMMA GEMM + fused tanh-dot epilogue.
// CTA: M=64 seq rows, N=256 (all h), K=256 in 8 tiles of 32, double-buffered.
// 8 warps: wm = wid&1 (rows 32), wn = wid>>1 (cols 64).
// acc = Ah*Bh + Ah*Bl + Al*Bh   (fp32 accum; lo*lo dropped ~2^-18)
// __launch_bounds__(256, 2): cap regs at 128 so 2 CTAs/SM co-reside.
// ---------------------------------------------------------------------------
#define MT 64
#define KT 32
#define PITCH 80          // bytes per smem row (32 bf16 + 8 pad)
// smem byte offsets
#define OFF_A   0         // A[s][t]: + (s*2+t)*5120     (64 rows * 80B)
#define OFF_B   20480     // B[s][t]: + (s*2+t)*20480    (256 rows * 80B)
#define OFF_IB  102400    // 256 floats
#define OFF_V   103424    // 256 floats
#define OFF_P   104448    // partial[64][4] floats
#define SMEM_TOTAL 105472

__global__ __launch_bounds__(256, 2) void k_main(const float* __restrict__ context,
                                                 const float* __restrict__ b_ctx,
                                                 const float* __restrict__ V) {
    extern __shared__ char smem[];
    uint32_t sb = smem_u32(smem);
    int tid = threadIdx.x;
    int wid = tid >> 5, lid = tid & 31;
    int wm = wid & 1, wn = wid >> 1;
    int b = blockIdx.y;
    int m0 = blockIdx.x * MT;

    float* ibs = (float*)(smem + OFF_IB);
    float* vvs = (float*)(smem + OFF_V);
    ibs[tid] = g_inp[b * HH + tid] + b_ctx[tid];
    vvs[tid] = V[tid];

    const float* ctx = context + ((long)b * SS + m0) * DD;

    // ---- A prefetch mapping: row = tid>>2, seg = tid&3 (8 floats each)
    int arow = tid >> 2, aseg = tid & 3;
    const float* aptr = ctx + arow * DD + aseg * 8;
    // ---- B cp.async mapping: 8 chunks of 16B per thread
    {
        int k0 = 0;
#pragma unroll
        for (int r = 0; r < 8; r++) {
            int idx = tid + 256 * r;
            int mat = idx >> 10, rem = idx & 1023;
            int row = rem >> 2, c = rem & 3;
            const __nv_bfloat16* src = (mat ? g_Bl : g_Bh) + row * DD + k0 + c * 8;
            uint32_t dst = sb + OFF_B + mat * 20480 + row * PITCH + c * 16;
            CP_ASYNC16(dst, src);
        }
        CP_COMMIT();
    }
    float4 a0 = *(const float4*)(aptr);
    float4 a1 = *(const float4*)(aptr + 4);

    float c[2][8][4];
#pragma unroll
    for (int mi = 0; mi < 2; mi++)
#pragma unroll
        for (int j = 0; j < 8; j++)
#pragma unroll
            for (int e = 0; e < 4; e++) c[mi][j][e] = 0.f;

    for (int kt = 0; kt < DD / KT; kt++) {
        int s = kt & 1;
        // ---- convert prefetched A (fp32 -> bf16 hi/lo) into stage s
        {
            float f[8] = {a0.x, a0.y, a0.z, a0.w, a1.x, a1.y, a1.z, a1.w};
            uint32_t hi[4], lo[4];
#pragma unroll
            for (int e = 0; e < 4; e++) {
                __nv_bfloat16 h0 = __float2bfloat16_rn(f[2*e]);
                __nv_bfloat16 h1 = __float2bfloat16_rn(f[2*e+1]);
                __nv_bfloat16 l0 = __float2bfloat16_rn(f[2*e]   - __bfloat162float(h0));
                __nv_bfloat16 l1 = __float2bfloat16_rn(f[2*e+1] - __bfloat162float(h1));
                hi[e] = (uint32_t)__bfloat16_as_ushort(h0) | ((uint32_t)__bfloat16_as_ushort(h1) << 16);
                lo[e] = (uint32_t)__bfloat16_as_ushort(l0) | ((uint32_t)__bfloat16_as_ushort(l1) << 16);
            }
            char* base = smem + OFF_A + s * 10240 + arow * PITCH + aseg * 16;
            *(uint4*)(base)         = make_uint4(hi[0], hi[1], hi[2], hi[3]);
            *(uint4*)(base + 5120)  = make_uint4(lo[0], lo[1], lo[2], lo[3]);
        }
        CP_WAIT0();
        __syncthreads();

        // ---- prefetch next stage
        if (kt < DD / KT - 1) {
            int k0 = (kt + 1) * KT;
#pragma unroll
            for (int r = 0; r < 8; r++) {
                int idx = tid + 256 * r;
                int mat = idx >> 10, rem = idx & 1023;
                int row = rem >> 2, cc = rem & 3;
                const __nv_bfloat16* src = (mat ? g_Bl : g_Bh) + row * DD + k0 + cc * 8;
                uint32_t dst = sb + OFF_B + (s ^ 1) * 2 * 20480 + mat * 20480 + row * PITCH + cc * 16;
                CP_ASYNC16(dst, src);
            }
            CP_COMMIT();
            const float* ap = ctx + arow * DD + k0 + aseg * 8;
            a0 = *(const float4*)(ap);
            a1 = *(const float4*)(ap + 4);
        }

        // ---- MMAs over stage s
        uint32_t abase = sb + OFF_A + s * 10240;
        uint32_t bbase = sb + OFF_B + s * 2 * 20480;
#pragma unroll
        for (int ks = 0; ks < 2; ks++) {
            uint32_t aH[2][4], aL[2][4], bH[4][4], bL[4][4];
            int arow_f = wm * 32 + (lid & 15);
            int acol_b = ks * 32 + (lid >> 4) * 16;
#pragma unroll
            for (int mi = 0; mi < 2; mi++) {
                uint32_t ad = abase + (arow_f + mi * 16) * PITCH + acol_b;
                LDSM4(aH[mi][0], aH[mi][1], aH[mi][2], aH[mi][3], ad);
                LDSM4(aL[mi][0], aL[mi][1], aL[mi][2], aL[mi][3], ad + 5120);
            }
            int brow_f = wn * 64 + (lid & 7) + ((lid >> 4) * 8);
            int bcol_b = ks * 32 + ((lid >> 3) & 1) * 16;
#pragma unroll
            for (int jp = 0; jp < 4; jp++) {
                uint32_t bd = bbase + (brow_f + jp * 16) * PITCH + bcol_b;
                LDSM4(bH[jp][0], bH[jp][1], bH[jp][2], bH[jp][3], bd);
                LDSM4(bL[jp][0], bL[jp][1], bL[jp][2], bL[jp][3], bd + 20480);
            }
#pragma unroll
            for (int mi = 0; mi < 2; mi++)
#pragma unroll
                for (int j = 0; j < 8; j++) {
                    uint32_t h0 = bH[j >> 1][(j & 1) * 2], h1 = bH[j >> 1][(j & 1) * 2 + 1];
                    uint32_t l0 = bL[j >> 1][(j & 1) * 2], l1 = bL[j >> 1][(j & 1) * 2 + 1];
                    MMA_BF16(c[mi][j], aH[mi], h0, h1);
                    MMA_BF16(c[mi][j], aH[mi], l0, l1);
                    MMA_BF16(c[mi][j], aL[mi], h0, h1);
                }
        }
    }

    // ---- epilogue: per-row tanh-dot with V
    {
        int q = lid & 3, g = lid >> 2;
        float ps[2][2] = {{0.f, 0.f}, {0.f, 0.f}};
#pragma unroll
        for (int mi = 0; mi < 2; mi++)
#pragma unroll
            for (int j = 0; j < 8; j++) {
                int h0 = wn * 64 + j * 8 + q * 2;
                ps[mi][0] += vvs[h0]   * tanhf(c[mi][j][0] + ibs[h0]);
                ps[mi][0] += vvs[h0+1] * tanhf(c[mi][j][1] + ibs[h0+1]);
                ps[mi][1] += vvs[h0]   * tanhf(c[mi][j][2] + ibs[h0]);
                ps[mi][1] += vvs[h0+1] * tanhf(c[mi][j][3] + ibs[h0+1]);
            }
#pragma unroll
        for (int off = 1; off <= 2; off <<= 1) {
#pragma unroll
            for (int mi = 0; mi < 2; mi++) {
                ps[mi][0] += __shfl_xor_sync(0xffffffffu, ps[mi][0], off);
                ps[mi][1] += __shfl_xor_sync(0xffffffffu, ps[mi][1], off);
            }
        }
        float* part = (float*)(smem + OFF_P);
        __syncthreads();
        if (q == 0) {
#pragma unroll
            for (int mi = 0; mi < 2; mi++) {
                part[(wm * 32 + mi * 16 + g) * 4 + wn]     = ps[mi][0];
                part[(wm * 32 + mi * 16 + g + 8) * 4 + wn] = ps[mi][1];
            }
        }
        __syncthreads();
        if (tid < MT) {
            float ssum = part[tid * 4] + part[tid * 4 + 1] + part[tid * 4 + 2] + part[tid * 4 + 3];
            g_att[b * SS + m0 + tid] = 10.f * tanhf(ssum);
        }
    }
}

// ---------------------------------------------------------------------------
// Kernel 4: mask echo + single-pass masked argmax + p = exp(max)/sum(exp).
// att in [-10,10] so exp() cannot overflow.
// ---------------------------------------------------------------------------
__global__ __launch_bounds__(1024) void k_reduce(const int* __restrict__ mask,
                                                 float* __restrict__ out) {
    int b = blockIdx.x, tid = threadIdx.x;
    __shared__ float smax[1024], ssum[1024];
    __shared__ int   sidx[1024];

    float best = -INFINITY, se = 0.f;
    int bidx = 0x7fffffff;
    for (int s = tid; s < SS; s += 1024) {
        int m = mask[b * SS + s];
        out[2 * BB + b * SS + s] = m ? 1.f : 0.f;
        if (m) {
            float v = g_att[b * SS + s];
            se += expf(v);
            if (v > best || (v == best && s < bidx)) { best = v; bidx = s; }
        }
    }
    smax[tid] = best; sidx[tid] = bidx; ssum[tid] = se;
    __syncthreads();
    for (int off = 512; off; off >>= 1) {
        if (tid < off) {
            float v = smax[tid + off]; int ix = sidx[tid + off];
            if (v > smax[tid] || (v == smax[tid] && ix < sidx[tid])) {
                smax[tid] = v; sidx[tid] = ix;
            }
            ssum[tid] += ssum[tid + off];
        }
        __syncthreads();
    }
    if (tid == 0) {
        float rowmax = smax[0];
        out[b]      = (float)((rowmax == -INFINITY) ? 0 : sidx[0]);
        out[BB + b] = expf(rowmax) / ssum[0];
    }
}

// ---------------------------------------------------------------------------
extern "C" void kernel_launch(void* const* d_in, const int* in_sizes, int n_in,
                              void* d_out, int out_size) {
    const float* x      = (const float*)d_in[0];
    const float* contex = (const float*)d_in[1];
    const int*   mask   = (const int*)  d_in[2];
    const float* W_in   = (const float*)d_in[3];
    const float* b_in   = (const float*)d_in[4];
    const float* W_ctx  = (const float*)d_in[5];
    const float* b_ctx  = (const float*)d_in[6];
    const float* V      = (const float*)d_in[7];
    float* out = (float*)d_out;

    cudaFuncSetAttribute(k_main, cudaFuncAttributeMaxDynamicSharedMemorySize, SMEM_TOTAL);

    k_inp<<<BB, HH>>>(x, W_in, b_in);
    k_wsplit<<<HH * DD / 256, 256>>>(W_ctx);
    k_main<<<dim3(SS / MT, BB), 256, SMEM_TOTAL>>>(contex, b_ctx, V);
    k_reduce<<<BB, 1024>>>(mask, out);
}